// round 3
// baseline (speedup 1.0000x reference)
#include <cuda_runtime.h>
#include <cstdint>

// Problem constants
#define BB   16
#define DD   512
#define TT   2048
#define KK   1024
#define NN   (BB*TT)          // 32768
#define NQ   (BB*DD*TT)       // 16777216

// Tiling for fused GEMM+argmin
#define TM   128              // rows (tokens) per block
#define TN   128              // codes per k-tile
#define TD   16               // D per smem stage (double-buffered)
#define NSTAGE (DD / TD)      // 32
#define NTHREADS 256

// ---------------- device scratch (allocation-free rule: static __device__) ----
__device__ float  g_wsq[KK];            // |w_k|^2
__device__ float  g_cbT[DD * KK];       // codebook transposed [d][k]
__device__ float  g_zsq[NN];            // |z_n|^2
__device__ int    g_idx[NN];            // argmin indices
__device__ double g_loss;               // loss accumulator

// ---------------- K0a: codebook prep (wsq + transpose) + zero loss -----------
__global__ void prep_codebook(const float* __restrict__ cb) {
    int k   = blockIdx.x;            // 0..1023
    int tid = threadIdx.x;           // 128 threads
    float s = 0.f;
    #pragma unroll
    for (int d = tid; d < DD; d += 128) {
        float v = cb[(size_t)k * DD + d];
        g_cbT[(size_t)d * KK + k] = v;
        s += v * v;
    }
    #pragma unroll
    for (int o = 16; o; o >>= 1) s += __shfl_xor_sync(0xffffffffu, s, o);
    __shared__ float ws[4];
    if ((tid & 31) == 0) ws[tid >> 5] = s;
    __syncthreads();
    if (tid == 0) {
        g_wsq[k] = (ws[0] + ws[1]) + (ws[2] + ws[3]);
        if (k == 0) g_loss = 0.0;
    }
}

// ---------------- K0b: per-row |z|^2 ------------------------------------------
__global__ void compute_zsq(const float* __restrict__ z) {
    // grid 256, block 128: block handles 128 consecutive t within one b
    int n0 = blockIdx.x * 128;
    int b  = n0 >> 11;                  // /2048
    int t  = (n0 & (TT - 1)) + threadIdx.x;
    const float* zb = z + (size_t)b * DD * TT + t;
    float s0 = 0.f, s1 = 0.f, s2 = 0.f, s3 = 0.f;
    #pragma unroll 4
    for (int d = 0; d < DD; d += 4) {
        float v0 = zb[(size_t)(d + 0) * TT];
        float v1 = zb[(size_t)(d + 1) * TT];
        float v2 = zb[(size_t)(d + 2) * TT];
        float v3 = zb[(size_t)(d + 3) * TT];
        s0 = fmaf(v0, v0, s0);
        s1 = fmaf(v1, v1, s1);
        s2 = fmaf(v2, v2, s2);
        s3 = fmaf(v3, v3, s3);
    }
    g_zsq[n0 + threadIdx.x] = (s0 + s1) + (s2 + s3);
}

// ---------------- K1: fused GEMM + argmin (double-buffered pipeline) ----------
// z layout [B, D, T] is already "A-transposed": row d of a t-tile is contiguous.
__global__ __launch_bounds__(NTHREADS) void vq_main(
    const float* __restrict__ z,
    const float* __restrict__ cb,
    float* __restrict__ out)
{
    __shared__ float As[2][TD][TM + 4];   // [buf][d][m]   16.9 KB
    __shared__ float Bs[2][TD][TN + 4];   // [buf][d][k]   16.9 KB

    int tid = threadIdx.x;
    int tx  = tid & 15;                // code group (8 codes)
    int ty  = tid >> 4;                // row group  (8 rows)
    int blk = blockIdx.x;              // 0..255
    int b   = blk >> 4;                // T/TM = 16 tiles per b
    int t0  = (blk & 15) * TM;
    const float* zb = z + (size_t)b * DD * TT + t0;

    // load-lane decomposition (2 float4s per thread per tile per stage)
    int a_d0  = (tid + 0)   >> 5;      // 0..7
    int a_d1  = (tid + 256) >> 5;      // 8..15
    int a_m4  = (tid & 31) * 4;        // 0..124
    int b_k0  = (tid + 0)   >> 2;      // 0..63
    int b_k1  = (tid + 256) >> 2;      // 64..127
    int b_dq  = (tid & 3) * 4;         // 0..12

    // per-thread row data
    float zsqr[8];
    #pragma unroll
    for (int i = 0; i < 8; i++)
        zsqr[i] = g_zsq[b * TT + t0 + ty * 8 + i];

    const float INF = __int_as_float(0x7f800000);
    float bestv[8];
    int   besti[8];
    #pragma unroll
    for (int i = 0; i < 8; i++) { bestv[i] = INF; besti[i] = 0; }

    #pragma unroll 1
    for (int kt = 0; kt < KK; kt += TN) {
        float acc[8][8];
        #pragma unroll
        for (int i = 0; i < 8; i++)
            #pragma unroll
            for (int j = 0; j < 8; j++) acc[i][j] = 0.f;

        float4 a4_0, a4_1, b4_0, b4_1;

        // ---- prologue: load + store stage 0 into buf 0 ----
        {
            a4_0 = *(const float4*)(zb + (size_t)a_d0 * TT + a_m4);
            a4_1 = *(const float4*)(zb + (size_t)a_d1 * TT + a_m4);
            b4_0 = *(const float4*)(cb + (size_t)(kt + b_k0) * DD + b_dq);
            b4_1 = *(const float4*)(cb + (size_t)(kt + b_k1) * DD + b_dq);
            // previous k-tile's loop ends with a __syncthreads(), so all
            // threads are done reading both buffers before this store.
            *(float4*)&As[0][a_d0][a_m4] = a4_0;
            *(float4*)&As[0][a_d1][a_m4] = a4_1;
            Bs[0][b_dq + 0][b_k0] = b4_0.x;
            Bs[0][b_dq + 1][b_k0] = b4_0.y;
            Bs[0][b_dq + 2][b_k0] = b4_0.z;
            Bs[0][b_dq + 3][b_k0] = b4_0.w;
            Bs[0][b_dq + 0][b_k1] = b4_1.x;
            Bs[0][b_dq + 1][b_k1] = b4_1.y;
            Bs[0][b_dq + 2][b_k1] = b4_1.z;
            Bs[0][b_dq + 3][b_k1] = b4_1.w;
            __syncthreads();
        }

        #pragma unroll 1
        for (int s = 0; s < NSTAGE; s++) {
            int cur = s & 1;
            // issue next stage's global loads before computing (latency overlap)
            if (s + 1 < NSTAGE) {
                int d0 = (s + 1) * TD;
                a4_0 = *(const float4*)(zb + (size_t)(d0 + a_d0) * TT + a_m4);
                a4_1 = *(const float4*)(zb + (size_t)(d0 + a_d1) * TT + a_m4);
                b4_0 = *(const float4*)(cb + (size_t)(kt + b_k0) * DD + d0 + b_dq);
                b4_1 = *(const float4*)(cb + (size_t)(kt + b_k1) * DD + d0 + b_dq);
            }
            #pragma unroll
            for (int d = 0; d < TD; d++) {
                float a[8], bv[8];
                *(float4*)&a[0]  = *(float4*)&As[cur][d][ty * 8];
                *(float4*)&a[4]  = *(float4*)&As[cur][d][ty * 8 + 4];
                *(float4*)&bv[0] = *(float4*)&Bs[cur][d][tx * 8];
                *(float4*)&bv[4] = *(float4*)&Bs[cur][d][tx * 8 + 4];
                #pragma unroll
                for (int i = 0; i < 8; i++)
                    #pragma unroll
                    for (int j = 0; j < 8; j++)
                        acc[i][j] = fmaf(a[i], bv[j], acc[i][j]);
            }
            __syncthreads();   // everyone done reading buf[cur]
            if (s + 1 < NSTAGE) {
                int nxt = cur ^ 1;
                *(float4*)&As[nxt][a_d0][a_m4] = a4_0;
                *(float4*)&As[nxt][a_d1][a_m4] = a4_1;
                Bs[nxt][b_dq + 0][b_k0] = b4_0.x;
                Bs[nxt][b_dq + 1][b_k0] = b4_0.y;
                Bs[nxt][b_dq + 2][b_k0] = b4_0.z;
                Bs[nxt][b_dq + 3][b_k0] = b4_0.w;
                Bs[nxt][b_dq + 0][b_k1] = b4_1.x;
                Bs[nxt][b_dq + 1][b_k1] = b4_1.y;
                Bs[nxt][b_dq + 2][b_k1] = b4_1.z;
                Bs[nxt][b_dq + 3][b_k1] = b4_1.w;
                __syncthreads();
            }
        }

        // epilogue: dist = fl(fl(z_sq - fl(2*s)) + w_sq), argmin w/ first-index ties
        int kbase = kt + tx * 8;
        float wq[8];
        #pragma unroll
        for (int j = 0; j < 8; j++) wq[j] = g_wsq[kbase + j];
        #pragma unroll
        for (int i = 0; i < 8; i++) {
            float lv = INF;
            int   li = 0;
            #pragma unroll
            for (int j = 0; j < 8; j++) {
                float v = __fadd_rn(__fsub_rn(zsqr[i], __fmul_rn(2.0f, acc[i][j])), wq[j]);
                if (v < lv) { lv = v; li = kbase + j; }   // j ascending: strict < keeps first
            }
            // reduce across the 16 tx-lanes (stays within a 16-lane half-warp)
            #pragma unroll
            for (int off = 8; off >= 1; off >>= 1) {
                float ov = __shfl_xor_sync(0xffffffffu, lv, off);
                int   oi = __shfl_xor_sync(0xffffffffu, li, off);
                if (ov < lv || (ov == lv && oi < li)) { lv = ov; li = oi; }
            }
            if (lv < bestv[i] || (lv == bestv[i] && li < besti[i])) {
                bestv[i] = lv;
                besti[i] = li;
            }
        }
        __syncthreads();   // buffers free for next k-tile's prologue store
    }

    if (tx == 0) {
        #pragma unroll
        for (int i = 0; i < 8; i++) {
            int n = b * TT + t0 + ty * 8 + i;
            g_idx[n] = besti[i];
            out[(size_t)NQ + n] = (float)besti[i];
        }
    }
}

// ---------------- K2: gather z_q, write z_q_st, loss partials ----------------
__global__ void gather_out(const float* __restrict__ z, float* __restrict__ out) {
    // grid B*D = 8192 blocks, 256 threads; block = one (b, d) row of T
    int bd = blockIdx.x;
    int b  = bd >> 9;          // /512
    int d  = bd & (DD - 1);
    __shared__ float row[KK];
    ((float4*)row)[threadIdx.x] = ((const float4*)(g_cbT + (size_t)d * KK))[threadIdx.x];
    __syncthreads();

    size_t base = ((size_t)b * DD + d) * TT;
    double lsum = 0.0;
    for (int c = 0; c < TT; c += 256) {
        int t    = c + threadIdx.x;
        int idx  = g_idx[b * TT + t];
        float zq = row[idx];
        float zv = z[base + t];
        // z + (z_q - z) with forced fp32 rounding order (matches reference STE)
        out[base + t] = __fadd_rn(zv, __fsub_rn(zq, zv));
        float df = __fsub_rn(zq, zv);
        lsum += (double)df * (double)df;
    }
    #pragma unroll
    for (int o = 16; o; o >>= 1) lsum += __shfl_xor_sync(0xffffffffu, lsum, o);
    __shared__ double red[8];
    if ((threadIdx.x & 31) == 0) red[threadIdx.x >> 5] = lsum;
    __syncthreads();
    if (threadIdx.x == 0) {
        double s = 0.0;
        #pragma unroll
        for (int i = 0; i < 8; i++) s += red[i];
        atomicAdd(&g_loss, s);
    }
}

// ---------------- K3: finalize loss ------------------------------------------
__global__ void finalize_loss(float* __restrict__ out) {
    // loss = (1 + BETA) * mean((z_q - z)^2), BETA = 0.25
    out[(size_t)NQ + NN] = (float)(g_loss * (1.25 / (double)NQ));
}

// ---------------- launch ------------------------------------------------------
extern "C" void kernel_launch(void* const* d_in, const int* in_sizes, int n_in,
                              void* d_out, int out_size) {
    const float* z  = (const float*)d_in[0];   // [16, 512, 2048] fp32
    const float* cb = (const float*)d_in[1];   // [1024, 512] fp32
    float* out = (float*)d_out;                // [z_q_st | indices | loss]

    prep_codebook<<<KK, 128>>>(cb);
    compute_zsq<<<NN / 128, 128>>>(z);
    vq_main<<<NN / TM, NTHREADS>>>(z, cb, out);
    gather_out<<<BB * DD, 256>>>(z, out);
    finalize_loss<<<1, 1>>>(out);
}

// round 4
// speedup vs baseline: 1.0201x; 1.0201x over previous
#include <cuda_runtime.h>
#include <cstdint>

// Problem constants
#define BB   16
#define DD   512
#define TT   2048
#define KK   1024
#define NN   (BB*TT)          // 32768
#define NQ   (BB*DD*TT)       // 16777216

// Tiling for fused GEMM+argmin
#define TM   128              // rows (tokens) per block
#define TN   128              // codes per k-tile
#define TD   16               // D per smem stage (double-buffered)
#define NSTAGE (DD / TD)      // 32
#define NTHREADS 256

typedef unsigned long long ull;

// packed f32x2 ops (Blackwell FFMA2 path — ptxas only emits via PTX f32x2)
#define FMA_F32X2(d, a, b, c) \
    asm("fma.rn.f32x2 %0, %1, %2, %3;" : "=l"(d) : "l"(a), "l"(b), "l"(c))
#define PACK_F32X2(out, lo, hi) \
    asm("mov.b64 %0, {%1, %2};" : "=l"(out) : "f"(lo), "f"(hi))
#define UNPACK_F32X2(lo, hi, in) \
    asm("mov.b64 {%0, %1}, %2;" : "=f"(lo), "=f"(hi) : "l"(in))

// ---------------- device scratch (allocation-free rule: static __device__) ----
__device__ float  g_wsq[KK];            // |w_k|^2
__device__ float  g_cbT[DD * KK];       // codebook transposed [d][k]
__device__ float  g_zsq[NN];            // |z_n|^2
__device__ int    g_idx[NN];            // argmin indices
__device__ double g_loss;               // loss accumulator

// ---------------- K0a: codebook prep (wsq + transpose) + zero loss -----------
__global__ void prep_codebook(const float* __restrict__ cb) {
    int k   = blockIdx.x;            // 0..1023
    int tid = threadIdx.x;           // 128 threads
    float s = 0.f;
    #pragma unroll
    for (int d = tid; d < DD; d += 128) {
        float v = cb[(size_t)k * DD + d];
        g_cbT[(size_t)d * KK + k] = v;
        s += v * v;
    }
    #pragma unroll
    for (int o = 16; o; o >>= 1) s += __shfl_xor_sync(0xffffffffu, s, o);
    __shared__ float ws[4];
    if ((tid & 31) == 0) ws[tid >> 5] = s;
    __syncthreads();
    if (tid == 0) {
        g_wsq[k] = (ws[0] + ws[1]) + (ws[2] + ws[3]);
        if (k == 0) g_loss = 0.0;
    }
}

// ---------------- K0b: per-row |z|^2 ------------------------------------------
__global__ void compute_zsq(const float* __restrict__ z) {
    int n0 = blockIdx.x * 128;
    int b  = n0 >> 11;                  // /2048
    int t  = (n0 & (TT - 1)) + threadIdx.x;
    const float* zb = z + (size_t)b * DD * TT + t;
    float s0 = 0.f, s1 = 0.f, s2 = 0.f, s3 = 0.f;
    #pragma unroll 4
    for (int d = 0; d < DD; d += 4) {
        float v0 = zb[(size_t)(d + 0) * TT];
        float v1 = zb[(size_t)(d + 1) * TT];
        float v2 = zb[(size_t)(d + 2) * TT];
        float v3 = zb[(size_t)(d + 3) * TT];
        s0 = fmaf(v0, v0, s0);
        s1 = fmaf(v1, v1, s1);
        s2 = fmaf(v2, v2, s2);
        s3 = fmaf(v3, v3, s3);
    }
    g_zsq[n0 + threadIdx.x] = (s0 + s1) + (s2 + s3);
}

// ---------------- K1: fused GEMM + argmin (FFMA2 double-pumped) ---------------
// z layout [B, D, T] is already "A-transposed": row d of a t-tile is contiguous.
__global__ __launch_bounds__(NTHREADS) void vq_main(
    const float* __restrict__ z,
    const float* __restrict__ cb,
    float* __restrict__ out)
{
    __shared__ float As[2][TD][TM + 4];   // [buf][d][m]   16.9 KB
    __shared__ float Bs[2][TD][TN + 4];   // [buf][d][k]   16.9 KB

    int tid = threadIdx.x;
    int tx  = tid & 15;                // code group (8 codes)
    int ty  = tid >> 4;                // row group  (8 rows)
    int blk = blockIdx.x;              // 0..255
    int b   = blk >> 4;                // T/TM = 16 tiles per b
    int t0  = (blk & 15) * TM;
    const float* zb = z + (size_t)b * DD * TT + t0;

    // load-lane decomposition (2 float4s per thread per tile per stage)
    int a_d0  = (tid + 0)   >> 5;      // 0..7
    int a_d1  = (tid + 256) >> 5;      // 8..15
    int a_m4  = (tid & 31) * 4;        // 0..124
    int b_k0  = (tid + 0)   >> 2;      // 0..63
    int b_k1  = (tid + 256) >> 2;      // 64..127
    int b_dq  = (tid & 3) * 4;         // 0..12

    // per-thread row data
    float zsqr[8];
    #pragma unroll
    for (int i = 0; i < 8; i++)
        zsqr[i] = g_zsq[b * TT + t0 + ty * 8 + i];

    const float INF = __int_as_float(0x7f800000);
    float bestv[8];
    int   besti[8];
    #pragma unroll
    for (int i = 0; i < 8; i++) { bestv[i] = INF; besti[i] = 0; }

    #pragma unroll 1
    for (int kt = 0; kt < KK; kt += TN) {
        // packed accumulators: acc2[i][jp] = {sum for j=2jp, sum for j=2jp+1}
        ull acc2[8][4];
        #pragma unroll
        for (int i = 0; i < 8; i++)
            #pragma unroll
            for (int jp = 0; jp < 4; jp++) acc2[i][jp] = 0ull;  // {0.f, 0.f}

        float4 a4_0, a4_1, b4_0, b4_1;

        // ---- prologue: load + store stage 0 into buf 0 ----
        {
            a4_0 = *(const float4*)(zb + (size_t)a_d0 * TT + a_m4);
            a4_1 = *(const float4*)(zb + (size_t)a_d1 * TT + a_m4);
            b4_0 = *(const float4*)(cb + (size_t)(kt + b_k0) * DD + b_dq);
            b4_1 = *(const float4*)(cb + (size_t)(kt + b_k1) * DD + b_dq);
            *(float4*)&As[0][a_d0][a_m4] = a4_0;
            *(float4*)&As[0][a_d1][a_m4] = a4_1;
            Bs[0][b_dq + 0][b_k0] = b4_0.x;
            Bs[0][b_dq + 1][b_k0] = b4_0.y;
            Bs[0][b_dq + 2][b_k0] = b4_0.z;
            Bs[0][b_dq + 3][b_k0] = b4_0.w;
            Bs[0][b_dq + 0][b_k1] = b4_1.x;
            Bs[0][b_dq + 1][b_k1] = b4_1.y;
            Bs[0][b_dq + 2][b_k1] = b4_1.z;
            Bs[0][b_dq + 3][b_k1] = b4_1.w;
            __syncthreads();
        }

        #pragma unroll 1
        for (int s = 0; s < NSTAGE; s++) {
            int cur = s & 1;
            // issue next stage's global loads before computing (latency overlap)
            if (s + 1 < NSTAGE) {
                int d0 = (s + 1) * TD;
                a4_0 = *(const float4*)(zb + (size_t)(d0 + a_d0) * TT + a_m4);
                a4_1 = *(const float4*)(zb + (size_t)(d0 + a_d1) * TT + a_m4);
                b4_0 = *(const float4*)(cb + (size_t)(kt + b_k0) * DD + d0 + b_dq);
                b4_1 = *(const float4*)(cb + (size_t)(kt + b_k1) * DD + d0 + b_dq);
            }
            #pragma unroll
            for (int d = 0; d < TD; d++) {
                // A fragment: 8 floats, each duplicated into an f32x2 pair
                float a[8];
                *(float4*)&a[0] = *(float4*)&As[cur][d][ty * 8];
                *(float4*)&a[4] = *(float4*)&As[cur][d][ty * 8 + 4];
                ull aa[8];
                #pragma unroll
                for (int i = 0; i < 8; i++) PACK_F32X2(aa[i], a[i], a[i]);
                // B fragment: 4 natural f32x2 pairs straight from smem
                ulonglong2 bp0 = *(const ulonglong2*)&Bs[cur][d][tx * 8];
                ulonglong2 bp1 = *(const ulonglong2*)&Bs[cur][d][tx * 8 + 4];
                ull b2[4] = { bp0.x, bp0.y, bp1.x, bp1.y };
                #pragma unroll
                for (int i = 0; i < 8; i++)
                    #pragma unroll
                    for (int jp = 0; jp < 4; jp++)
                        FMA_F32X2(acc2[i][jp], aa[i], b2[jp], acc2[i][jp]);
            }
            __syncthreads();   // everyone done reading buf[cur]
            if (s + 1 < NSTAGE) {
                int nxt = cur ^ 1;
                *(float4*)&As[nxt][a_d0][a_m4] = a4_0;
                *(float4*)&As[nxt][a_d1][a_m4] = a4_1;
                Bs[nxt][b_dq + 0][b_k0] = b4_0.x;
                Bs[nxt][b_dq + 1][b_k0] = b4_0.y;
                Bs[nxt][b_dq + 2][b_k0] = b4_0.z;
                Bs[nxt][b_dq + 3][b_k0] = b4_0.w;
                Bs[nxt][b_dq + 0][b_k1] = b4_1.x;
                Bs[nxt][b_dq + 1][b_k1] = b4_1.y;
                Bs[nxt][b_dq + 2][b_k1] = b4_1.z;
                Bs[nxt][b_dq + 3][b_k1] = b4_1.w;
                __syncthreads();
            }
        }

        // epilogue: dist = fl(fl(z_sq - fl(2*s)) + w_sq), argmin w/ first-index ties
        int kbase = kt + tx * 8;
        float wq[8];
        #pragma unroll
        for (int j = 0; j < 8; j++) wq[j] = g_wsq[kbase + j];
        #pragma unroll
        for (int i = 0; i < 8; i++) {
            float accf[8];
            #pragma unroll
            for (int jp = 0; jp < 4; jp++)
                UNPACK_F32X2(accf[2 * jp], accf[2 * jp + 1], acc2[i][jp]);
            float lv = INF;
            int   li = 0;
            #pragma unroll
            for (int j = 0; j < 8; j++) {
                float v = __fadd_rn(__fsub_rn(zsqr[i], __fmul_rn(2.0f, accf[j])), wq[j]);
                if (v < lv) { lv = v; li = kbase + j; }   // j ascending: strict < keeps first
            }
            // reduce across the 16 tx-lanes (stays within a 16-lane half-warp)
            #pragma unroll
            for (int off = 8; off >= 1; off >>= 1) {
                float ov = __shfl_xor_sync(0xffffffffu, lv, off);
                int   oi = __shfl_xor_sync(0xffffffffu, li, off);
                if (ov < lv || (ov == lv && oi < li)) { lv = ov; li = oi; }
            }
            if (lv < bestv[i] || (lv == bestv[i] && li < besti[i])) {
                bestv[i] = lv;
                besti[i] = li;
            }
        }
        __syncthreads();   // buffers free for next k-tile's prologue store
    }

    if (tx == 0) {
        #pragma unroll
        for (int i = 0; i < 8; i++) {
            int n = b * TT + t0 + ty * 8 + i;
            g_idx[n] = besti[i];
            out[(size_t)NQ + n] = (float)besti[i];
        }
    }
}

// ---------------- K2: gather z_q, write z_q_st, loss partials ----------------
__global__ void gather_out(const float* __restrict__ z, float* __restrict__ out) {
    // grid B*D = 8192 blocks, 256 threads; block = one (b, d) row of T
    int bd = blockIdx.x;
    int b  = bd >> 9;          // /512
    int d  = bd & (DD - 1);
    __shared__ float row[KK];
    ((float4*)row)[threadIdx.x] = ((const float4*)(g_cbT + (size_t)d * KK))[threadIdx.x];
    __syncthreads();

    size_t base = ((size_t)b * DD + d) * TT;
    // front-batch all 8 index loads + 8 z loads (independent LDGs, MLP=8)
    int   idxs[8];
    float zv[8];
    #pragma unroll
    for (int r = 0; r < 8; r++) {
        int t  = r * 256 + threadIdx.x;
        idxs[r] = g_idx[b * TT + t];
        zv[r]   = z[base + t];
    }
    double lsum = 0.0;
    #pragma unroll
    for (int r = 0; r < 8; r++) {
        int t    = r * 256 + threadIdx.x;
        float zq = row[idxs[r]];
        // z + (z_q - z) with forced fp32 rounding order (matches reference STE)
        out[base + t] = __fadd_rn(zv[r], __fsub_rn(zq, zv[r]));
        float df = __fsub_rn(zq, zv[r]);
        lsum += (double)df * (double)df;
    }
    #pragma unroll
    for (int o = 16; o; o >>= 1) lsum += __shfl_xor_sync(0xffffffffu, lsum, o);
    __shared__ double red[8];
    if ((threadIdx.x & 31) == 0) red[threadIdx.x >> 5] = lsum;
    __syncthreads();
    if (threadIdx.x == 0) {
        double s = 0.0;
        #pragma unroll
        for (int i = 0; i < 8; i++) s += red[i];
        atomicAdd(&g_loss, s);
    }
}

// ---------------- K3: finalize loss ------------------------------------------
__global__ void finalize_loss(float* __restrict__ out) {
    // loss = (1 + BETA) * mean((z_q - z)^2), BETA = 0.25
    out[(size_t)NQ + NN] = (float)(g_loss * (1.25 / (double)NQ));
}

// ---------------- launch ------------------------------------------------------
extern "C" void kernel_launch(void* const* d_in, const int* in_sizes, int n_in,
                              void* d_out, int out_size) {
    const float* z  = (const float*)d_in[0];   // [16, 512, 2048] fp32
    const float* cb = (const float*)d_in[1];   // [1024, 512] fp32
    float* out = (float*)d_out;                // [z_q_st | indices | loss]

    prep_codebook<<<KK, 128>>>(cb);
    compute_zsq<<<NN / 128, 128>>>(z);
    vq_main<<<NN / TM, NTHREADS>>>(z, cb, out);
    gather_out<<<BB * DD, 256>>>(z, out);
    finalize_loss<<<1, 1>>>(out);
}

// round 7
// speedup vs baseline: 1.3368x; 1.3104x over previous
#include <cuda_runtime.h>
#include <cstdint>

// ---------------- problem constants ----------------
#define BB   16
#define DD   512
#define TT   2048
#define KK   1024
#define NN   (BB*TT)          // 32768
#define NQ   (BB*DD*TT)       // 16777216

// ---------------- tiling ----------------
#define M_TILE   128          // tokens per CTA
#define N_TILE   128          // codes per n-tile
#define NT_COUNT (KK / N_TILE)   // 8
#define D_STAGE  32           // D elems per smem stage
#define N_STAGES (DD / D_STAGE)  // 16
#define THREADS  256

// smem strides (floats), padded for alignment + bank behavior
#define ZS_LD   132           // 528B row stride (16B aligned)
#define BS_LD   36            // 144B row stride (16B aligned)
#define ZS_BYTES (D_STAGE * ZS_LD * 4)      // 16896
#define BS_BYTES (N_TILE * BS_LD * 4)       // 18432
#define DYN_SMEM (2*ZS_BYTES + 2*BS_BYTES)  // 70656

typedef unsigned long long ull;

// ---------------- PTX helpers (arch-neutral: compute_80+) ----------------
__device__ __forceinline__ uint32_t smem_u32(const void* p) {
    uint32_t a;
    asm("{ .reg .u64 t; cvta.to.shared.u64 t, %1; cvt.u32.u64 %0, t; }" : "=r"(a) : "l"(p));
    return a;
}
#define CP_ASYNC16(dst, src) asm volatile("cp.async.cg.shared.global [%0], [%1], 16;" :: "r"(dst), "l"(src))
#define CP_COMMIT()          asm volatile("cp.async.commit_group;" ::: "memory")
#define CP_WAIT1()           asm volatile("cp.async.wait_group 1;" ::: "memory")
#define CP_WAIT0()           asm volatile("cp.async.wait_group 0;" ::: "memory")

__device__ __forceinline__ uint32_t to_tf32(float v) {
    uint32_t r;
    asm("cvt.rna.tf32.f32 %0, %1;" : "=r"(r) : "f"(v));
    return r;
}
__device__ __forceinline__ void split_tf32(float v, uint32_t& hi, uint32_t& lo) {
    hi = to_tf32(v);
    lo = to_tf32(__fsub_rn(v, __uint_as_float(hi)));
}
#define MMA_TF32(c0,c1,c2,c3, a0,a1,a2,a3, b0,b1) \
    asm volatile("mma.sync.aligned.m16n8k8.row.col.f32.tf32.tf32.f32 " \
        "{%0,%1,%2,%3}, {%4,%5,%6,%7}, {%8,%9}, {%0,%1,%2,%3};" \
        : "+f"(c0), "+f"(c1), "+f"(c2), "+f"(c3) \
        : "r"(a0), "r"(a1), "r"(a2), "r"(a3), "r"(b0), "r"(b1))

// ---------------- device scratch (static: allocation-free rule) ---------------
__device__ float  g_cbT[DD * KK];     // codebook transposed (gather cache)
__device__ float  g_wsq[KK];
__device__ float  g_zsq[NN];
__device__ int    g_idx[NN];
__device__ double g_loss;

// ---------------- K0a: codebook prep (wsq + transpose) + zero loss -----------
__global__ void prep_codebook(const float* __restrict__ cb) {
    int k   = blockIdx.x;
    int tid = threadIdx.x;      // 128
    float s = 0.f;
    for (int d = tid; d < DD; d += 128) {
        float v = cb[(size_t)k * DD + d];
        g_cbT[(size_t)d * KK + k] = v;
        s += v * v;
    }
    #pragma unroll
    for (int o = 16; o; o >>= 1) s += __shfl_xor_sync(0xffffffffu, s, o);
    __shared__ float ws[4];
    if ((tid & 31) == 0) ws[tid >> 5] = s;
    __syncthreads();
    if (tid == 0) {
        g_wsq[k] = (ws[0] + ws[1]) + (ws[2] + ws[3]);
        if (k == 0) g_loss = 0.0;
    }
}

// ---------------- K0b: per-row |z|^2 ------------------------------------------
__global__ void compute_zsq(const float* __restrict__ z) {
    int n0 = blockIdx.x * 128;
    int b  = n0 >> 11;
    int t  = (n0 & (TT - 1)) + threadIdx.x;
    const float* zb = z + (size_t)b * DD * TT + t;
    float s0 = 0.f, s1 = 0.f, s2 = 0.f, s3 = 0.f;
    #pragma unroll 4
    for (int d = 0; d < DD; d += 4) {
        float v0 = zb[(size_t)(d + 0) * TT];
        float v1 = zb[(size_t)(d + 1) * TT];
        float v2 = zb[(size_t)(d + 2) * TT];
        float v3 = zb[(size_t)(d + 3) * TT];
        s0 = fmaf(v0, v0, s0);
        s1 = fmaf(v1, v1, s1);
        s2 = fmaf(v2, v2, s2);
        s3 = fmaf(v3, v3, s3);
    }
    g_zsq[n0 + threadIdx.x] = (s0 + s1) + (s2 + s3);
}

// ---------------- K1: 3xTF32 mma.sync GEMM + argmin ---------------------------
__global__ __launch_bounds__(THREADS)
void vq_mma(const float* __restrict__ z,
            const float* __restrict__ cb,
            float* __restrict__ out)
{
    extern __shared__ char dyn[];
    __shared__ float sWsq[KK];
    __shared__ ull   sRed[M_TILE][2];

    const uint32_t dynb = smem_u32(dyn);
    int tid  = threadIdx.x;
    int wid  = tid >> 5;
    int lane = tid & 31;
    int q    = lane & 3;           // thread-in-group
    int r4   = lane >> 2;          // group id
    int warpM  = (wid & 3) * 32;   // 4 M-bands
    int warpNb = wid >> 2;         // 2 N-bands
    int warpN  = warpNb * 64;

    int n0 = blockIdx.x * M_TILE;
    int b  = n0 >> 11;                 // /TT
    int t0 = n0 & (TT - 1);
    const float* zb = z + (size_t)b * DD * TT + t0;

    // wsq -> smem
    #pragma unroll
    for (int i = 0; i < 4; i++) sWsq[tid + i * 256] = g_wsq[tid + i * 256];

    // per-thread row squared norms (4 rows owned in epilogue math)
    float zsqr[4];
    #pragma unroll
    for (int mi = 0; mi < 2; mi++)
        #pragma unroll
        for (int h = 0; h < 2; h++)
            zsqr[mi * 2 + h] = g_zsq[n0 + warpM + 16 * mi + 8 * h + r4];

    ull bestAll = 0xffffffffffffffffULL;   // running (distbits<<32 | idx)

    // cp.async lane decomposition
    // A stage: 32 d-rows x 128 floats = 1024 x 16B; 4 per thread
    int a_d[4], a_m4[4];
    // B stage: 128 n-rows x 32 floats = 1024 x 16B; 4 per thread
    int b_n[4], b_c4[4];
    #pragma unroll
    for (int i = 0; i < 4; i++) {
        int u = tid + i * 256;
        a_d[i]  = u >> 5;              // 0..31
        a_m4[i] = (u & 31) * 4;        // 0..124
        b_n[i]  = u >> 3;              // 0..127
        b_c4[i] = (u & 7) * 4;         // 0..28
    }

    __syncthreads();

    #pragma unroll 1
    for (int nt = 0; nt < NT_COUNT; nt++) {
        int kb0 = nt * N_TILE;
        float acc[2][8][4];
        #pragma unroll
        for (int mi = 0; mi < 2; mi++)
            #pragma unroll
            for (int nf = 0; nf < 8; nf++)
                #pragma unroll
                for (int e = 0; e < 4; e++) acc[mi][nf][e] = 0.f;

        // ---- prologue: stage 0 -> buf 0 ----
        {
            uint32_t zdst = dynb;                       // Zs buf0
            uint32_t bdst = dynb + 2 * ZS_BYTES;        // Bs buf0
            #pragma unroll
            for (int i = 0; i < 4; i++)
                CP_ASYNC16(zdst + a_d[i] * (ZS_LD * 4) + a_m4[i] * 4,
                           zb + (size_t)a_d[i] * TT + a_m4[i]);
            #pragma unroll
            for (int i = 0; i < 4; i++)
                CP_ASYNC16(bdst + b_n[i] * (BS_LD * 4) + b_c4[i] * 4,
                           cb + (size_t)(kb0 + b_n[i]) * DD + b_c4[i]);
            CP_COMMIT();
        }

        #pragma unroll 1
        for (int s = 0; s < N_STAGES; s++) {
            int cur = s & 1;
            if (s + 1 < N_STAGES) {
                int nx = cur ^ 1;
                int d0 = (s + 1) * D_STAGE;
                uint32_t zdst = dynb + nx * ZS_BYTES;
                uint32_t bdst = dynb + 2 * ZS_BYTES + nx * BS_BYTES;
                #pragma unroll
                for (int i = 0; i < 4; i++)
                    CP_ASYNC16(zdst + a_d[i] * (ZS_LD * 4) + a_m4[i] * 4,
                               zb + (size_t)(d0 + a_d[i]) * TT + a_m4[i]);
                #pragma unroll
                for (int i = 0; i < 4; i++)
                    CP_ASYNC16(bdst + b_n[i] * (BS_LD * 4) + b_c4[i] * 4,
                               cb + (size_t)(kb0 + b_n[i]) * DD + d0 + b_c4[i]);
                CP_COMMIT();
                CP_WAIT1();
            } else {
                CP_WAIT0();
            }
            __syncthreads();

            const float* Zs = (const float*)(dyn + cur * ZS_BYTES);
            const float* Bs = (const float*)(dyn + 2 * ZS_BYTES + cur * BS_BYTES);

            #pragma unroll
            for (int j = 0; j < 4; j++) {
                // A fragments for both m-frags: split fp32 -> tf32 hi/lo
                uint32_t ah[2][4], al[2][4];
                #pragma unroll
                for (int mi = 0; mi < 2; mi++) {
                    int rm = warpM + 16 * mi + r4;
                    #pragma unroll
                    for (int e = 0; e < 4; e++) {
                        int dd = 8 * j + q + (e >> 1) * 4;
                        int mm = rm + (e & 1) * 8;
                        split_tf32(Zs[dd * ZS_LD + mm], ah[mi][e], al[mi][e]);
                    }
                }
                #pragma unroll
                for (int nf = 0; nf < 8; nf++) {
                    int nn = warpN + 8 * nf + r4;
                    uint32_t bh0, bl0, bh1, bl1;
                    split_tf32(Bs[nn * BS_LD + 8 * j + q],     bh0, bl0);
                    split_tf32(Bs[nn * BS_LD + 8 * j + q + 4], bh1, bl1);
                    #pragma unroll
                    for (int mi = 0; mi < 2; mi++) {
                        float* c = acc[mi][nf];
                        MMA_TF32(c[0], c[1], c[2], c[3],
                                 ah[mi][0], ah[mi][1], ah[mi][2], ah[mi][3], bh0, bh1);
                        MMA_TF32(c[0], c[1], c[2], c[3],
                                 ah[mi][0], ah[mi][1], ah[mi][2], ah[mi][3], bl0, bl1);
                        MMA_TF32(c[0], c[1], c[2], c[3],
                                 al[mi][0], al[mi][1], al[mi][2], al[mi][3], bh0, bh1);
                    }
                }
            }
            __syncthreads();
        }

        // ---- epilogue: dist + argmin for this n-tile ----
        #pragma unroll
        for (int mi = 0; mi < 2; mi++) {
            #pragma unroll
            for (int h = 0; h < 2; h++) {
                int  rloc = warpM + 16 * mi + 8 * h + r4;
                float zs  = zsqr[mi * 2 + h];
                ull best  = 0xffffffffffffffffULL;
                #pragma unroll
                for (int nf = 0; nf < 8; nf++) {
                    int col = kb0 + warpN + 8 * nf + 2 * q;
                    float s0 = acc[mi][nf][2 * h + 0];
                    float s1 = acc[mi][nf][2 * h + 1];
                    float v0 = __fadd_rn(__fsub_rn(zs, __fmul_rn(2.0f, s0)), sWsq[col]);
                    float v1 = __fadd_rn(__fsub_rn(zs, __fmul_rn(2.0f, s1)), sWsq[col + 1]);
                    ull p0 = ((ull)__float_as_uint(v0) << 32) | (uint32_t)col;
                    ull p1 = ((ull)__float_as_uint(v1) << 32) | (uint32_t)(col + 1);
                    if (p0 < best) best = p0;
                    if (p1 < best) best = p1;
                }
                // quad reduce (lanes 4r..4r+3 share the same row)
                ull o1 = __shfl_xor_sync(0xffffffffu, best, 1);
                if (o1 < best) best = o1;
                ull o2 = __shfl_xor_sync(0xffffffffu, best, 2);
                if (o2 < best) best = o2;
                if (q == 0) sRed[rloc][warpNb] = best;
            }
        }
        __syncthreads();
        if (tid < M_TILE) {
            ull m0 = sRed[tid][0], m1 = sRed[tid][1];
            ull m  = m0 < m1 ? m0 : m1;
            if (m < bestAll) bestAll = m;
        }
        __syncthreads();
    }

    if (tid < M_TILE) {
        int idx = (int)(uint32_t)(bestAll & 0xffffffffULL);
        g_idx[n0 + tid] = idx;
        out[(size_t)NQ + n0 + tid] = (float)idx;
    }
}

// ---------------- K2: gather z_q, write z_q_st, loss partials ----------------
__global__ void gather_out(const float* __restrict__ z, float* __restrict__ out) {
    int bd = blockIdx.x;
    int b  = bd >> 9;
    int d  = bd & (DD - 1);
    __shared__ float row[KK];
    ((float4*)row)[threadIdx.x] = ((const float4*)(g_cbT + (size_t)d * KK))[threadIdx.x];
    __syncthreads();

    size_t base = ((size_t)b * DD + d) * TT;
    int   idxs[8];
    float zv[8];
    #pragma unroll
    for (int r = 0; r < 8; r++) {
        int t  = r * 256 + threadIdx.x;
        idxs[r] = g_idx[b * TT + t];
        zv[r]   = z[base + t];
    }
    double lsum = 0.0;
    #pragma unroll
    for (int r = 0; r < 8; r++) {
        int t    = r * 256 + threadIdx.x;
        float zq = row[idxs[r]];
        out[base + t] = __fadd_rn(zv[r], __fsub_rn(zq, zv[r]));
        float df = __fsub_rn(zq, zv[r]);
        lsum += (double)df * (double)df;
    }
    #pragma unroll
    for (int o = 16; o; o >>= 1) lsum += __shfl_xor_sync(0xffffffffu, lsum, o);
    __shared__ double red[8];
    if ((threadIdx.x & 31) == 0) red[threadIdx.x >> 5] = lsum;
    __syncthreads();
    if (threadIdx.x == 0) {
        double s = 0.0;
        #pragma unroll
        for (int i = 0; i < 8; i++) s += red[i];
        atomicAdd(&g_loss, s);
    }
}

// ---------------- K3: finalize loss ------------------------------------------
__global__ void finalize_loss(float* __restrict__ out) {
    out[(size_t)NQ + NN] = (float)(g_loss * (1.25 / (double)NQ));
}

// ---------------- launch ------------------------------------------------------
extern "C" void kernel_launch(void* const* d_in, const int* in_sizes, int n_in,
                              void* d_out, int out_size) {
    const float* z  = (const float*)d_in[0];   // [16, 512, 2048] fp32
    const float* cb = (const float*)d_in[1];   // [1024, 512] fp32
    float* out = (float*)d_out;                // [z_q_st | indices | loss]

    cudaFuncSetAttribute(vq_mma, cudaFuncAttributeMaxDynamicSharedMemorySize, DYN_SMEM);

    prep_codebook<<<KK, 128>>>(cb);
    compute_zsq<<<NN / 128, 128>>>(z);
    vq_mma<<<NN / M_TILE, THREADS, DYN_SMEM>>>(z, cb, out);
    gather_out<<<BB * DD, 256>>>(z, out);
    finalize_loss<<<1, 1>>>(out);
}